// round 14
// baseline (speedup 1.0000x reference)
#include <cuda_runtime.h>
#include <math.h>

#define Bb 64
#define Tt 2048
#define Vv 256
#define Uu 256
#define NEGV (-1e30f)

__device__ float g_nll[Bb];
__device__ int   g_done;        // zero-init; self-resetting

__device__ __forceinline__ void cp16(unsigned sa, const float* g) {
    asm volatile("cp.async.cg.shared.global [%0], [%1], 16;\n" :: "r"(sa), "l"(g) : "memory");
}
__device__ __forceinline__ void cpcommit() {
    asm volatile("cp.async.commit_group;\n" ::: "memory");
}
template<int N> __device__ __forceinline__ void cpwait() {
    asm volatile("cp.async.wait_group %0;\n" :: "n"(N) : "memory");
}
__device__ __forceinline__ void strel(unsigned a, int v) {
    asm volatile("st.release.cta.shared.b32 [%0], %1;" :: "r"(a), "r"(v) : "memory");
}
__device__ __forceinline__ int ldacq(unsigned a) {
    int v;
    asm volatile("ld.acquire.cta.shared.b32 %0, [%1];" : "=r"(v) : "r"(a) : "memory");
    return v;
}
__device__ __forceinline__ void spinw(unsigned a, int need) {
    if (ldacq(a) >= need) return;
    do { __nanosleep(32); } while (ldacq(a) < need);
}

// smem layout (bytes from dynamic base)
#define OFF_RING   0            // 64 slots x 1KB f32 d-rows             = 65536
#define OFF_LOG    65536        // 6 producers x 16 slots x 1KB          = 98304
#define OFF_BND    163840       // (Tt+8) f32                            = 8224
#define OFF_TGT    172064       // 256 int                               = 1024
#define OFF_EO     173088       // 520 f32 (sE[258] | sO[256])           = 2080
#define OFF_DUMP   175168       // 32 f32                                = 128
#define OFF_CB     175296       // 6 f32 (pad 32)                        = 32
#define OFF_PP     175328       // 6 int producer progress (pad 32)      = 32
#define OFF_CP     175360       // DP-hi progress                        = 4
#define OFF_DP     175364       // DP-lo progress                        = 4
#define SMEM_TOTAL 175616

// ===========================================================================
// Fused kernel: one block per batch, 10 warps.
//  wids 0,1,4,5,8,9: producers (SMSPs 0,1,0,1,0,1), 16-slot staging each
//  wid 2:            DP lo (pairs 0..127)       -- PRIVATE SMSP 2
//  wid 3:            DP hi (pairs 128..255+512) -- PRIVATE SMSP 3
//  wids 6,7:         park at final barrier
//  Last block folds the global reduction (no finalize launch).
// ===========================================================================
__global__ void __launch_bounds__(320, 1) fused_kernel(const float* __restrict__ logits,
                                                       const int*  __restrict__ targets,
                                                       const int*  __restrict__ loglen,
                                                       const int*  __restrict__ tgtlen,
                                                       float* __restrict__ out) {
    extern __shared__ char sm[];
    char*  sRing = sm + OFF_RING;
    float* sLog  = (float*)(sm + OFF_LOG);
    float* sBnd  = (float*)(sm + OFF_BND);
    int*   sTgt  = (int*)(sm + OFF_TGT);
    float* sEO   = (float*)(sm + OFF_EO);
    float* sDump = (float*)(sm + OFF_DUMP);
    float* sCb   = (float*)(sm + OFF_CB);
    const unsigned ppBase = (unsigned)__cvta_generic_to_shared(sm + OFF_PP);
    const unsigned cpAddr = (unsigned)__cvta_generic_to_shared(sm + OFF_CP);
    const unsigned dpAddr = (unsigned)__cvta_generic_to_shared(sm + OFF_DP);

    const int tid  = threadIdx.x;
    const int wid  = tid >> 5;
    const int lane = tid & 31;
    const int b    = blockIdx.x;
    const int L    = loglen[b];
    const int Ut   = tgtlen[b];

    // block init
    if (tid < 256) sTgt[tid] = targets[b * Uu + tid];
    if (tid < 6) { ((int*)(sm + OFF_PP))[tid] = 0; sCb[tid] = 0.0f; }
    if (tid == 0) { *(int*)(sm + OFF_CP) = 0; *(int*)(sm + OFF_DP) = 0; sBnd[0] = NEGV; }
    __syncthreads();

    const bool isProd = (wid == 0 || wid == 1 || wid == 4 || wid == 5 || wid == 8 || wid == 9);

    if (isProd) {
        // ==================================================================
        // PRODUCER pidx 0..5: chunks pidx, pidx+6, ... (8 rows each;
        // 2 rows/iter; 16-slot staging, 14-row cp.async lead)
        // ==================================================================
        const int pidx = (wid >> 2) * 2 + (wid & 1);
        const float* lgB = logits + (size_t)b * Tt * Vv;
        float* stage = sLog + pidx * (16 * 256);
        const unsigned stageB = (unsigned)__cvta_generic_to_shared(stage);
        const unsigned ppA = ppBase + (unsigned)pidx * 4u;
        const int4 tg0 = *(const int4*)&sTgt[lane * 8];
        const int4 tg1 = *(const int4*)&sTgt[lane * 8 + 4];

#define ROWOF(J) (8 * pidx + 48 * ((J) >> 3) + ((J) & 7))
        // prologue: prefetch j = 0..13 (one group each)
#pragma unroll
        for (int p = 0; p < 14; ++p) {
            int r = ROWOF(p);
            if (r < L) {
                unsigned sa = stageB + ((unsigned)p << 10) + (unsigned)lane * 32u;
                const float* g = lgB + (size_t)r * Vv + lane * 8;
                cp16(sa, g); cp16(sa + 16, g + 4);
            }
            cpcommit();
        }

        float cb = 0.0f;
        for (int j = 0; ; j += 2) {
            const int rA = ROWOF(j);
            if (rA >= L) break;
            const int rB = rA + 1;            // same chunk ((j&7) even <= 6)
            const bool bval = (rB < L);

            // prefetch j+14, j+15
            {
                int r14 = ROWOF(j + 14);
                if (r14 < L) {
                    unsigned sa = stageB + ((unsigned)((j + 14) & 15) << 10) + (unsigned)lane * 32u;
                    const float* g = lgB + (size_t)r14 * Vv + lane * 8;
                    cp16(sa, g); cp16(sa + 16, g + 4);
                }
                cpcommit();
                int r15 = ROWOF(j + 15);
                if (r15 < L) {
                    unsigned sa = stageB + ((unsigned)((j + 15) & 15) << 10) + (unsigned)lane * 32u;
                    const float* g = lgB + (size_t)r15 * Vv + lane * 8;
                    cp16(sa, g); cp16(sa + 16, g + 4);
                }
                cpcommit();
            }
            cpwait<14>();         // rows j, j+1 staged
            __syncwarp();

            // backpressure: ring has 64 slots; row r needs DP-hi past row r-64
            {
                int rmax = bval ? rB : rA;
                if (rmax >= 64) spinw(cpAddr, (rmax - 32) >> 5);
            }

            const float* ra = stage + (j & 15) * 256;
            const float* rb = stage + ((j + 1) & 15) * 256;
            float4 a0 = *(const float4*)&ra[lane * 4];
            float4 a1 = *(const float4*)&ra[128 + lane * 4];
            float4 b0 = *(const float4*)&rb[lane * 4];
            float4 b1 = *(const float4*)&rb[128 + lane * 4];
            float sa = __expf(a0.x) + __expf(a0.y) + __expf(a0.z) + __expf(a0.w)
                     + __expf(a1.x) + __expf(a1.y) + __expf(a1.z) + __expf(a1.w);
            float sb = __expf(b0.x) + __expf(b0.y) + __expf(b0.z) + __expf(b0.w)
                     + __expf(b1.x) + __expf(b1.y) + __expf(b1.z) + __expf(b1.w);
#pragma unroll
            for (int o = 16; o; o >>= 1) {      // two independent chains overlap
                sa += __shfl_xor_sync(0xffffffffu, sa, o);
                sb += __shfl_xor_sync(0xffffffffu, sb, o);
            }
            float r0a = __shfl_sync(0xffffffffu, a0.x, 0);
            float r0b = __shfl_sync(0xffffffffu, b0.x, 0);
            cb += r0a - __logf(sa);
            if (bval) cb += r0b - __logf(sb);

            {
                float* rowp = (float*)(sRing + (((unsigned)rA & 63u) << 10));
                float4 d0, d1;
                d0.x = ra[tg0.x] - r0a;  d0.y = ra[tg0.y] - r0a;
                d0.z = ra[tg0.z] - r0a;  d0.w = ra[tg0.w] - r0a;
                d1.x = ra[tg1.x] - r0a;  d1.y = ra[tg1.y] - r0a;
                d1.z = ra[tg1.z] - r0a;  d1.w = ra[tg1.w] - r0a;
                *(float4*)(rowp + lane * 8)     = d0;
                *(float4*)(rowp + lane * 8 + 4) = d1;
            }
            if (bval) {
                float* rowp = (float*)(sRing + (((unsigned)rB & 63u) << 10));
                float4 d0, d1;
                d0.x = rb[tg0.x] - r0b;  d0.y = rb[tg0.y] - r0b;
                d0.z = rb[tg0.z] - r0b;  d0.w = rb[tg0.w] - r0b;
                d1.x = rb[tg1.x] - r0b;  d1.y = rb[tg1.y] - r0b;
                d1.z = rb[tg1.z] - r0b;  d1.w = rb[tg1.w] - r0b;
                *(float4*)(rowp + lane * 8)     = d0;
                *(float4*)(rowp + lane * 8 + 4) = d1;
            }

            // release chunk when complete (row 6/7 pair done, or last rows)
            if (((j & 7) == 6) || (ROWOF(j + 2) >= L)) {
                __syncwarp();
                if (lane == 0) strel(ppA, (j >> 3) + 1);
            }
        }
        if (lane == 0) sCb[pidx] = cb;
#undef ROWOF
    } else if (wid == 2 || wid == 3) {
        // ==================================================================
        // CONSUMER: DP. role 0 = wid2 (lo, SMSP2), role 1 = wid3 (hi, SMSP3)
        // ==================================================================
        const int role = wid - 2;
        const int l4 = lane * 4;
        const int pbase = role * 128 + l4;
        const unsigned roleOff = (unsigned)role << 9;     // 512 bytes
        const unsigned bndB = (unsigned)__cvta_generic_to_shared(sBnd);

        float gate[4];
        {
            int prev = (pbase == 0) ? -1 : sTgt[pbase - 1];
#pragma unroll
            for (int jj = 0; jj < 4; ++jj) {
                int cur = sTgt[pbase + jj];
                gate[jj] = (pbase + jj >= 1 && cur != prev) ? 0.0f : NEGV;
                prev = cur;
            }
        }
        float E[4], O[4];
#pragma unroll
        for (int jj = 0; jj < 4; ++jj) { E[jj] = NEGV; O[jj] = NEGV; }
        if (pbase == 0) E[0] = 0.0f;
        float Eex = NEGV, pO_cur = NEGV;
        const float pOmask = (lane == 0) ? NEGV : 0.0f;
        const unsigned stBase = (lane == 31) ? bndB
                               : (unsigned)__cvta_generic_to_shared(&sDump[lane]);
        const unsigned stStep = (lane == 31) ? 4u : 0u;

        float buf[4][4];
#define LDCONV(DST, SLOT)                                                     \
        {                                                                     \
            float4 v_ = *(const float4*)(sRing + ((unsigned)(SLOT) << 10) + roleOff + ((unsigned)lane << 4)); \
            (DST)[0] = v_.x; (DST)[1] = v_.y; (DST)[2] = v_.z; (DST)[3] = v_.w; \
        }
#define WAITCHUNK(C) spinw(ppBase + (unsigned)((C) % 6) * 4u, (C) / 6 + 1)

#define SUB0(T)                                                               \
        {                                                                     \
            LDCONV(buf[((T) + 2) & 3], (((T) + 2) & 63));                     \
            const float* dv = buf[(T) & 3];                                   \
            float e3 = E[3], o3 = O[3];                                       \
            float O3n = fmaxf(fmaxf(o3, e3), O[2] + gate[3]) + dv[3];         \
            float E3n = fmaxf(e3, O[2]);                                      \
            float nextPO = __shfl_up_sync(0xffffffffu, O3n, 1);               \
            unsigned dst_ = stBase + (unsigned)((T) + 1) * stStep;            \
            asm volatile("st.shared.b32 [%0], %1;" :: "r"(dst_), "f"(O3n));   \
            float pO = pO_cur;                                                \
            _Pragma("unroll")                                                 \
            for (int jj = 0; jj < 3; ++jj) {                                  \
                float e = E[jj], o = O[jj];                                   \
                E[jj] = fmaxf(e, pO);                                         \
                O[jj] = fmaxf(fmaxf(o, e), pO + gate[jj]) + dv[jj];           \
                pO = o;                                                       \
            }                                                                 \
            E[3] = E3n; O[3] = O3n;                                           \
            pO_cur = nextPO + pOmask;                                         \
        }

#define SUB1(T)                                                               \
        {                                                                     \
            LDCONV(buf[((T) + 2) & 3], (((T) + 2) & 63));                     \
            float bn = sBnd[(T) + 1];                                         \
            const float* dv = buf[(T) & 3];                                   \
            float e3 = E[3], o3 = O[3];                                       \
            float O3n = fmaxf(fmaxf(o3, e3), O[2] + gate[3]) + dv[3];         \
            float E3n = fmaxf(e3, O[2]);                                      \
            float nextPO = __shfl_up_sync(0xffffffffu, O3n, 1);               \
            Eex = fmaxf(Eex, o3);                                             \
            float pO = pO_cur;                                                \
            _Pragma("unroll")                                                 \
            for (int jj = 0; jj < 3; ++jj) {                                  \
                float e = E[jj], o = O[jj];                                   \
                E[jj] = fmaxf(e, pO);                                         \
                O[jj] = fmaxf(fmaxf(o, e), pO + gate[jj]) + dv[jj];           \
                pO = o;                                                       \
            }                                                                 \
            E[3] = E3n; O[3] = O3n;                                           \
            pO_cur = (lane == 0) ? bn : nextPO;                               \
        }

        const int ncfull = L >> 5;
        const int rem32  = L & 31;
        int t = 0;

        if (role == 0) {
            WAITCHUNK(0); WAITCHUNK(1);
            __syncwarp();
            LDCONV(buf[0], 0); LDCONV(buf[1], 1);
            for (int c = 0; c < ncfull; ++c) {
                for (int q = 0; q < 4; ++q) {
                    int gc = c * 4 + q;
                    if (8 * (gc + 1) < L) { WAITCHUNK(gc + 1); __syncwarp(); }
                    SUB0(t); SUB0(t + 1); SUB0(t + 2); SUB0(t + 3);
                    SUB0(t + 4); SUB0(t + 5); SUB0(t + 6); SUB0(t + 7);
                    t += 8;
                }
                if (lane == 31) strel(dpAddr, c + 1);
            }
            if (rem32) {
                int lastChunk = (L - 1) >> 3;
                for (int cc = 4 * ncfull; cc <= lastChunk; ++cc) WAITCHUNK(cc);
                __syncwarp();
                for (int k = 0; k < rem32; ++k) { SUB0(t); ++t; }
                if (lane == 31) strel(dpAddr, ncfull + 1);
            }
        } else {
            for (int c = 0; c < ncfull; ++c) {
                spinw(dpAddr, c + 1);
                __syncwarp();
                if (c == 0) { LDCONV(buf[0], 0); LDCONV(buf[1], 1); }
                for (int q = 0; q < 4; ++q) {
                    SUB1(t); SUB1(t + 1); SUB1(t + 2); SUB1(t + 3);
                    SUB1(t + 4); SUB1(t + 5); SUB1(t + 6); SUB1(t + 7);
                    t += 8;
                }
                __syncwarp();
                if (lane == 31) strel(cpAddr, c + 1);
            }
            if (rem32) {
                spinw(dpAddr, ncfull + 1);
                __syncwarp();
                for (int k = 0; k < rem32; ++k) { SUB1(t); ++t; }
            }
        }
#undef SUB0
#undef SUB1
#undef WAITCHUNK
#undef LDCONV

        float* sE = sEO;
        float* sO = sEO + 258;
#pragma unroll
        for (int jj = 0; jj < 4; ++jj) { sE[pbase + jj] = E[jj]; sO[pbase + jj] = O[jj]; }
        if (role == 1 && lane == 31) sE[256] = Eex;
    }
    // wids 6,7 fall through directly: parked at the barrier

    __syncthreads();
    if (wid == 2) {
        if (lane == 0) {
            float Cacc = sCb[0] + sCb[1] + sCb[2] + sCb[3] + sCb[4] + sCb[5];
            float vb = sEO[Ut];              // alpha_hat[2*Ut]
            float vl = sEO[258 + Ut - 1];    // alpha_hat[2*Ut - 1]
            g_nll[b] = -(fmaxf(vb, vl) + Cacc);
            __threadfence();
        }
        int last = 0;
        if (lane == 0) last = (atomicAdd(&g_done, 1) == Bb - 1) ? 1 : 0;
        last = __shfl_sync(0xffffffffu, last, 0);
        if (last) {
            __threadfence();                 // acquire all blocks' g_nll
            float s = 0.0f, c = 0.0f;
            for (int bb = lane; bb < Bb; bb += 32) { s += g_nll[bb]; c += (float)loglen[bb]; }
#pragma unroll
            for (int o = 16; o; o >>= 1) {
                s += __shfl_xor_sync(0xffffffffu, s, o);
                c += __shfl_xor_sync(0xffffffffu, c, o);
            }
            if (lane == 0) { out[0] = s / c; g_done = 0; }
        }
    }
}

// ---------------------------------------------------------------------------
extern "C" void kernel_launch(void* const* d_in, const int* in_sizes, int n_in,
                              void* d_out, int out_size) {
    const float* logits  = (const float*)d_in[0];
    const int*   targets = (const int*)d_in[1];
    const int*   loglen  = (const int*)d_in[2];
    const int*   tgtlen  = (const int*)d_in[3];

    cudaFuncSetAttribute(fused_kernel, cudaFuncAttributeMaxDynamicSharedMemorySize, SMEM_TOTAL);
    fused_kernel<<<Bb, 320, SMEM_TOTAL>>>(logits, targets, loglen, tgtlen, (float*)d_out);
}

// round 15
// speedup vs baseline: 1.6924x; 1.6924x over previous
#include <cuda_runtime.h>
#include <cuda_fp16.h>
#include <math.h>

#define Bb 64
#define Tt 2048
#define Vv 256
#define Uu 256
#define NEGV (-1e30f)

__device__ float g_nll[Bb];
__device__ int   g_done;        // zero-init; self-resetting

__device__ __forceinline__ void cp16(unsigned sa, const float* g) {
    asm volatile("cp.async.cg.shared.global [%0], [%1], 16;\n" :: "r"(sa), "l"(g) : "memory");
}
__device__ __forceinline__ void cpcommit() {
    asm volatile("cp.async.commit_group;\n" ::: "memory");
}
template<int N> __device__ __forceinline__ void cpwait() {
    asm volatile("cp.async.wait_group %0;\n" :: "n"(N) : "memory");
}
__device__ __forceinline__ void strel(unsigned a, int v) {
    asm volatile("st.release.cta.shared.b32 [%0], %1;" :: "r"(a), "r"(v) : "memory");
}
__device__ __forceinline__ int ldacq(unsigned a) {
    int v;
    asm volatile("ld.acquire.cta.shared.b32 %0, [%1];" : "=r"(v) : "r"(a) : "memory");
    return v;
}
__device__ __forceinline__ void spinw(unsigned a, int need) {
    if (ldacq(a) >= need) return;
    do { __nanosleep(32); } while (ldacq(a) < need);
}

// smem layout (bytes from dynamic base)
#define OFF_RING   0            // 128 slots x 512B fp16 d-rows          = 65536
#define OFF_LOG    65536        // 6 producers x 16 slots x 1KB          = 98304
#define OFF_BND    163840       // (Tt+8) f32                            = 8224
#define OFF_TGT    172064       // 256 int                               = 1024
#define OFF_EO     173088       // 520 f32 (sE[258] | sO[256])           = 2080
#define OFF_DUMP   175168       // 32 f32                                = 128
#define OFF_CB     175296       // 6 f32 (pad 32)                        = 32
#define OFF_PP     175328       // 6 int producer progress (pad 32)      = 32
#define OFF_CP     175360       // DP-hi progress                        = 4
#define OFF_DP     175364       // DP-lo progress                        = 4
#define SMEM_TOTAL 175616

// ===========================================================================
// Fused kernel: one block per batch, 10 warps.
//  wids 0,1,4,5,8,9: producers (SMSPs 0,1 only), 16-slot staging each
//  wid 2:            DP lo (pairs 0..127)       -- PRIVATE SMSP 2
//  wid 3:            DP hi (pairs 128..255+512) -- PRIVATE SMSP 3
//  wids 6,7:         park at final barrier
//  Ring: 128 fp16 rows -> producers run 96..127 rows ahead (R12 slack).
// ===========================================================================
__global__ void __launch_bounds__(320, 1) fused_kernel(const float* __restrict__ logits,
                                                       const int*  __restrict__ targets,
                                                       const int*  __restrict__ loglen,
                                                       const int*  __restrict__ tgtlen,
                                                       float* __restrict__ out) {
    extern __shared__ char sm[];
    char*  sRing = sm + OFF_RING;
    float* sLog  = (float*)(sm + OFF_LOG);
    float* sBnd  = (float*)(sm + OFF_BND);
    int*   sTgt  = (int*)(sm + OFF_TGT);
    float* sEO   = (float*)(sm + OFF_EO);
    float* sDump = (float*)(sm + OFF_DUMP);
    float* sCb   = (float*)(sm + OFF_CB);
    const unsigned ppBase = (unsigned)__cvta_generic_to_shared(sm + OFF_PP);
    const unsigned cpAddr = (unsigned)__cvta_generic_to_shared(sm + OFF_CP);
    const unsigned dpAddr = (unsigned)__cvta_generic_to_shared(sm + OFF_DP);

    const int tid  = threadIdx.x;
    const int wid  = tid >> 5;
    const int lane = tid & 31;
    const int b    = blockIdx.x;
    const int L    = loglen[b];
    const int Ut   = tgtlen[b];

    // block init
    if (tid < 256) sTgt[tid] = targets[b * Uu + tid];
    if (tid < 6) { ((int*)(sm + OFF_PP))[tid] = 0; sCb[tid] = 0.0f; }
    if (tid == 0) { *(int*)(sm + OFF_CP) = 0; *(int*)(sm + OFF_DP) = 0; sBnd[0] = NEGV; }
    __syncthreads();

    const bool isProd = (wid == 0 || wid == 1 || wid == 4 || wid == 5 || wid == 8 || wid == 9);

    if (isProd) {
        // ==================================================================
        // PRODUCER pidx 0..5: chunks pidx, pidx+6, ... (8 rows each;
        // 2 rows/iter; 16-slot staging, 14-row cp.async lead)
        // ==================================================================
        const int pidx = (wid >> 2) * 2 + (wid & 1);
        const float* lgB = logits + (size_t)b * Tt * Vv;
        float* stage = sLog + pidx * (16 * 256);
        const unsigned stageB = (unsigned)__cvta_generic_to_shared(stage);
        const unsigned ppA = ppBase + (unsigned)pidx * 4u;
        const int4 tg0 = *(const int4*)&sTgt[lane * 8];
        const int4 tg1 = *(const int4*)&sTgt[lane * 8 + 4];

#define ROWOF(J) (8 * pidx + 48 * ((J) >> 3) + ((J) & 7))
#pragma unroll
        for (int p = 0; p < 14; ++p) {
            int r = ROWOF(p);
            if (r < L) {
                unsigned sa = stageB + ((unsigned)p << 10) + (unsigned)lane * 32u;
                const float* g = lgB + (size_t)r * Vv + lane * 8;
                cp16(sa, g); cp16(sa + 16, g + 4);
            }
            cpcommit();
        }

        float cb = 0.0f;
        for (int j = 0; ; j += 2) {
            const int rA = ROWOF(j);
            if (rA >= L) break;
            const int rB = rA + 1;            // same chunk ((j&7) even <= 6)
            const bool bval = (rB < L);

            {
                int r14 = ROWOF(j + 14);
                if (r14 < L) {
                    unsigned sa = stageB + ((unsigned)((j + 14) & 15) << 10) + (unsigned)lane * 32u;
                    const float* g = lgB + (size_t)r14 * Vv + lane * 8;
                    cp16(sa, g); cp16(sa + 16, g + 4);
                }
                cpcommit();
                int r15 = ROWOF(j + 15);
                if (r15 < L) {
                    unsigned sa = stageB + ((unsigned)((j + 15) & 15) << 10) + (unsigned)lane * 32u;
                    const float* g = lgB + (size_t)r15 * Vv + lane * 8;
                    cp16(sa, g); cp16(sa + 16, g + 4);
                }
                cpcommit();
            }
            cpwait<14>();         // rows j, j+1 staged
            __syncwarp();

            // backpressure: 128-slot ring; row r collides with r-128.
            // Gate: DP-hi progress >= (r-96)>>5  ->  96..127 rows of slack.
            {
                int rmax = bval ? rB : rA;
                if (rmax >= 128) spinw(cpAddr, (rmax - 96) >> 5);
            }

            const float* ra = stage + (j & 15) * 256;
            const float* rb = stage + ((j + 1) & 15) * 256;
            float4 a0 = *(const float4*)&ra[lane * 4];
            float4 a1 = *(const float4*)&ra[128 + lane * 4];
            float4 b0 = *(const float4*)&rb[lane * 4];
            float4 b1 = *(const float4*)&rb[128 + lane * 4];
            float sa = __expf(a0.x) + __expf(a0.y) + __expf(a0.z) + __expf(a0.w)
                     + __expf(a1.x) + __expf(a1.y) + __expf(a1.z) + __expf(a1.w);
            float sb = __expf(b0.x) + __expf(b0.y) + __expf(b0.z) + __expf(b0.w)
                     + __expf(b1.x) + __expf(b1.y) + __expf(b1.z) + __expf(b1.w);
#pragma unroll
            for (int o = 16; o; o >>= 1) {
                sa += __shfl_xor_sync(0xffffffffu, sa, o);
                sb += __shfl_xor_sync(0xffffffffu, sb, o);
            }
            float r0a = __shfl_sync(0xffffffffu, a0.x, 0);
            float r0b = __shfl_sync(0xffffffffu, b0.x, 0);
            cb += r0a - __logf(sa);
            if (bval) cb += r0b - __logf(sb);

            {
                __half2 h0 = __floats2half2_rn(ra[tg0.x] - r0a, ra[tg0.y] - r0a);
                __half2 h1 = __floats2half2_rn(ra[tg0.z] - r0a, ra[tg0.w] - r0a);
                __half2 h2 = __floats2half2_rn(ra[tg1.x] - r0a, ra[tg1.y] - r0a);
                __half2 h3 = __floats2half2_rn(ra[tg1.z] - r0a, ra[tg1.w] - r0a);
                uint4 pk;
                pk.x = *(unsigned*)&h0; pk.y = *(unsigned*)&h1;
                pk.z = *(unsigned*)&h2; pk.w = *(unsigned*)&h3;
                *(uint4*)(sRing + (((unsigned)rA & 127u) << 9) + (unsigned)lane * 16u) = pk;
            }
            if (bval) {
                __half2 h0 = __floats2half2_rn(rb[tg0.x] - r0b, rb[tg0.y] - r0b);
                __half2 h1 = __floats2half2_rn(rb[tg0.z] - r0b, rb[tg0.w] - r0b);
                __half2 h2 = __floats2half2_rn(rb[tg1.x] - r0b, rb[tg1.y] - r0b);
                __half2 h3 = __floats2half2_rn(rb[tg1.z] - r0b, rb[tg1.w] - r0b);
                uint4 pk;
                pk.x = *(unsigned*)&h0; pk.y = *(unsigned*)&h1;
                pk.z = *(unsigned*)&h2; pk.w = *(unsigned*)&h3;
                *(uint4*)(sRing + (((unsigned)rB & 127u) << 9) + (unsigned)lane * 16u) = pk;
            }

            if (((j & 7) == 6) || (ROWOF(j + 2) >= L)) {
                __syncwarp();
                if (lane == 0) strel(ppA, (j >> 3) + 1);
            }
        }
        if (lane == 0) sCb[pidx] = cb;
#undef ROWOF
    } else if (wid == 2 || wid == 3) {
        // ==================================================================
        // CONSUMER: DP. role 0 = wid2 (lo, SMSP2), role 1 = wid3 (hi, SMSP3)
        // ==================================================================
        const int role = wid - 2;
        const int l4 = lane * 4;
        const int pbase = role * 128 + l4;
        const unsigned roleOff = (unsigned)role << 8;     // 256 bytes (fp16)
        const unsigned bndB = (unsigned)__cvta_generic_to_shared(sBnd);

        float gate[4];
        {
            int prev = (pbase == 0) ? -1 : sTgt[pbase - 1];
#pragma unroll
            for (int jj = 0; jj < 4; ++jj) {
                int cur = sTgt[pbase + jj];
                gate[jj] = (pbase + jj >= 1 && cur != prev) ? 0.0f : NEGV;
                prev = cur;
            }
        }
        float E[4], O[4];
#pragma unroll
        for (int jj = 0; jj < 4; ++jj) { E[jj] = NEGV; O[jj] = NEGV; }
        if (pbase == 0) E[0] = 0.0f;
        float Eex = NEGV, pO_cur = NEGV;
        const float pOmask = (lane == 0) ? NEGV : 0.0f;
        const unsigned stBase = (lane == 31) ? bndB
                               : (unsigned)__cvta_generic_to_shared(&sDump[lane]);
        const unsigned stStep = (lane == 31) ? 4u : 0u;

        float buf[4][4];
#define LDCONV(DST, SLOT)                                                     \
        {                                                                     \
            uint2 v_ = *(const uint2*)(sRing + ((unsigned)(SLOT) << 9) + roleOff + ((unsigned)lane << 3)); \
            float2 f0_ = __half22float2(*(__half2*)&v_.x);                    \
            float2 f1_ = __half22float2(*(__half2*)&v_.y);                    \
            (DST)[0] = f0_.x; (DST)[1] = f0_.y; (DST)[2] = f1_.x; (DST)[3] = f1_.y; \
        }
#define WAITCHUNK(C) spinw(ppBase + (unsigned)((C) % 6) * 4u, (C) / 6 + 1)

#define SUB0(T)                                                               \
        {                                                                     \
            LDCONV(buf[((T) + 2) & 3], (((T) + 2) & 127));                    \
            const float* dv = buf[(T) & 3];                                   \
            float e3 = E[3], o3 = O[3];                                       \
            float O3n = fmaxf(fmaxf(o3, e3), O[2] + gate[3]) + dv[3];         \
            float E3n = fmaxf(e3, O[2]);                                      \
            float nextPO = __shfl_up_sync(0xffffffffu, O3n, 1);               \
            unsigned dst_ = stBase + (unsigned)((T) + 1) * stStep;            \
            asm volatile("st.shared.b32 [%0], %1;" :: "r"(dst_), "f"(O3n));   \
            float pO = pO_cur;                                                \
            _Pragma("unroll")                                                 \
            for (int jj = 0; jj < 3; ++jj) {                                  \
                float e = E[jj], o = O[jj];                                   \
                E[jj] = fmaxf(e, pO);                                         \
                O[jj] = fmaxf(fmaxf(o, e), pO + gate[jj]) + dv[jj];           \
                pO = o;                                                       \
            }                                                                 \
            E[3] = E3n; O[3] = O3n;                                           \
            pO_cur = nextPO + pOmask;                                         \
        }

#define SUB1(T)                                                               \
        {                                                                     \
            LDCONV(buf[((T) + 2) & 3], (((T) + 2) & 127));                    \
            float bn = sBnd[(T) + 1];                                         \
            const float* dv = buf[(T) & 3];                                   \
            float e3 = E[3], o3 = O[3];                                       \
            float O3n = fmaxf(fmaxf(o3, e3), O[2] + gate[3]) + dv[3];         \
            float E3n = fmaxf(e3, O[2]);                                      \
            float nextPO = __shfl_up_sync(0xffffffffu, O3n, 1);               \
            Eex = fmaxf(Eex, o3);                                             \
            float pO = pO_cur;                                                \
            _Pragma("unroll")                                                 \
            for (int jj = 0; jj < 3; ++jj) {                                  \
                float e = E[jj], o = O[jj];                                   \
                E[jj] = fmaxf(e, pO);                                         \
                O[jj] = fmaxf(fmaxf(o, e), pO + gate[jj]) + dv[jj];           \
                pO = o;                                                       \
            }                                                                 \
            E[3] = E3n; O[3] = O3n;                                           \
            pO_cur = (lane == 0) ? bn : nextPO;                               \
        }

        const int ncfull = L >> 5;
        const int rem32  = L & 31;
        int t = 0;

        if (role == 0) {
            WAITCHUNK(0); WAITCHUNK(1);
            __syncwarp();
            LDCONV(buf[0], 0); LDCONV(buf[1], 1);
            for (int c = 0; c < ncfull; ++c) {
                for (int q = 0; q < 4; ++q) {
                    int gc = c * 4 + q;
                    if (8 * (gc + 1) < L) { WAITCHUNK(gc + 1); __syncwarp(); }
                    SUB0(t); SUB0(t + 1); SUB0(t + 2); SUB0(t + 3);
                    SUB0(t + 4); SUB0(t + 5); SUB0(t + 6); SUB0(t + 7);
                    t += 8;
                }
                if (lane == 31) strel(dpAddr, c + 1);
            }
            if (rem32) {
                int lastChunk = (L - 1) >> 3;
                for (int cc = 4 * ncfull; cc <= lastChunk; ++cc) WAITCHUNK(cc);
                __syncwarp();
                for (int k = 0; k < rem32; ++k) { SUB0(t); ++t; }
                if (lane == 31) strel(dpAddr, ncfull + 1);
            }
        } else {
            for (int c = 0; c < ncfull; ++c) {
                spinw(dpAddr, c + 1);
                __syncwarp();
                if (c == 0) { LDCONV(buf[0], 0); LDCONV(buf[1], 1); }
                for (int q = 0; q < 4; ++q) {
                    SUB1(t); SUB1(t + 1); SUB1(t + 2); SUB1(t + 3);
                    SUB1(t + 4); SUB1(t + 5); SUB1(t + 6); SUB1(t + 7);
                    t += 8;
                }
                __syncwarp();
                if (lane == 31) strel(cpAddr, c + 1);
            }
            if (rem32) {
                spinw(dpAddr, ncfull + 1);
                __syncwarp();
                for (int k = 0; k < rem32; ++k) { SUB1(t); ++t; }
            }
        }
#undef SUB0
#undef SUB1
#undef WAITCHUNK
#undef LDCONV

        float* sE = sEO;
        float* sO = sEO + 258;
#pragma unroll
        for (int jj = 0; jj < 4; ++jj) { sE[pbase + jj] = E[jj]; sO[pbase + jj] = O[jj]; }
        if (role == 1 && lane == 31) sE[256] = Eex;
    }
    // wids 6,7 fall through directly: parked at the barrier

    __syncthreads();
    if (wid == 2) {
        if (lane == 0) {
            float Cacc = sCb[0] + sCb[1] + sCb[2] + sCb[3] + sCb[4] + sCb[5];
            float vb = sEO[Ut];              // alpha_hat[2*Ut]
            float vl = sEO[258 + Ut - 1];    // alpha_hat[2*Ut - 1]
            g_nll[b] = -(fmaxf(vb, vl) + Cacc);
            __threadfence();
        }
        int last = 0;
        if (lane == 0) last = (atomicAdd(&g_done, 1) == Bb - 1) ? 1 : 0;
        last = __shfl_sync(0xffffffffu, last, 0);
        if (last) {
            __threadfence();                 // acquire all blocks' g_nll
            float s = 0.0f, c = 0.0f;
            for (int bb = lane; bb < Bb; bb += 32) { s += g_nll[bb]; c += (float)loglen[bb]; }
#pragma unroll
            for (int o = 16; o; o >>= 1) {
                s += __shfl_xor_sync(0xffffffffu, s, o);
                c += __shfl_xor_sync(0xffffffffu, c, o);
            }
            if (lane == 0) { out[0] = s / c; g_done = 0; }
        }
    }
}

// ---------------------------------------------------------------------------
extern "C" void kernel_launch(void* const* d_in, const int* in_sizes, int n_in,
                              void* d_out, int out_size) {
    const float* logits  = (const float*)d_in[0];
    const int*   targets = (const int*)d_in[1];
    const int*   loglen  = (const int*)d_in[2];
    const int*   tgtlen  = (const int*)d_in[3];

    cudaFuncSetAttribute(fused_kernel, cudaFuncAttributeMaxDynamicSharedMemorySize, SMEM_TOTAL);
    fused_kernel<<<Bb, 320, SMEM_TOTAL>>>(logits, targets, loglen, tgtlen, (float*)d_out);
}